// round 15
// baseline (speedup 1.0000x reference)
#include <cuda_runtime.h>
#include <cuda_fp16.h>
#include <math.h>
#include <stdint.h>

#define BN_EPS 1e-5f
#define ATTN_SCALE 0.0625f   // 1/sqrt(256)

// ---------------- scratch (device globals; no allocation) ----------------
__device__ float  g_qkv  [16u*768u*4096u];     // [b,768,h,w]  (q|k|v) fp32
__device__ float  g_qkvT [16u*768u*4096u];     // [b,768,w,h]  fp32
__device__ __half g_vP   [16u*4096u*512u];     // [b,pix,512]  (vh|vw) fp16
__device__ uint2  g_xP   [16u*256u*4096u];     // [b,ci,pix] -> 4 fp16 (khw patch)
__device__ uint4  g_wqkvP[196608u];            // [(kc*768+oc)*8+g]*2 + {hi,lo}
__device__ uint4  g_wprojP[32768u];            // [(kc*256+oc)*8+g]*2 + {hi,lo}

// ======================= warp-MMA helpers (base-ISA only) =================
__device__ __forceinline__ uint32_t smem_u32(const void* p) {
    uint32_t a;
    asm("{ .reg .u64 t; cvta.to.shared.u64 t, %1; cvt.u32.u64 %0, t; }"
        : "=r"(a) : "l"(p));
    return a;
}

__device__ __forceinline__ void ldsm4(uint32_t addr, uint32_t* r) {
    asm volatile("ldmatrix.sync.aligned.m8n8.x4.shared.b16 {%0,%1,%2,%3}, [%4];"
        : "=r"(r[0]), "=r"(r[1]), "=r"(r[2]), "=r"(r[3]) : "r"(addr));
}

__device__ __forceinline__ void mma16816(float* c, const uint32_t* a,
                                         uint32_t b0, uint32_t b1) {
    asm volatile(
        "mma.sync.aligned.m16n8k16.row.col.f32.f16.f16.f32 "
        "{%0,%1,%2,%3}, {%4,%5,%6,%7}, {%8,%9}, {%0,%1,%2,%3};"
        : "+f"(c[0]), "+f"(c[1]), "+f"(c[2]), "+f"(c[3])
        : "r"(a[0]), "r"(a[1]), "r"(a[2]), "r"(a[3]), "r"(b0), "r"(b1));
}

// 8 consecutive floats -> fp16 hi uint4 + fp16 lo (residual) uint4
__device__ __forceinline__ void split8(const float* f, uint4& hi, uint4& lo) {
    uint32_t h[4], l[4];
#pragma unroll
    for (int j = 0; j < 4; ++j) {
        __half2 hh = __floats2half2_rn(f[2*j], f[2*j+1]);
        float ra = f[2*j]   - __low2float(hh);
        float rb = f[2*j+1] - __high2float(hh);
        __half2 ll = __floats2half2_rn(ra, rb);
        h[j] = *(uint32_t*)&hh;
        l[j] = *(uint32_t*)&ll;
    }
    hi = make_uint4(h[0], h[1], h[2], h[3]);
    lo = make_uint4(l[0], l[1], l[2], l[3]);
}

// smem layout for GEMM kernels (K-chunk = 64 fp16, rows padded to 144B)
#define RB      144
#define OFF_AH  0
#define OFF_AL  18432
#define OFF_BH  36864
#define GEMM_SMEM 55296

// =========================================================================
// Kernel 0a: convert weights -> packed fp16 hi/lo, chunk-major
// =========================================================================
__global__ __launch_bounds__(256) void cvt_w_kernel(
    const float* __restrict__ wq, const float* __restrict__ wp)
{
    int gid = blockIdx.x * 256 + threadIdx.x;
    if (gid < 98304) {                       // w_qkv: 768 oc x 1024 k
        int g = gid & 7, t = gid >> 3;
        int oc = t % 768, kc = t / 768;
        float f[8];
        *(float4*)&f[0] = *(const float4*)(wq + (size_t)oc*1024 + kc*64 + g*8);
        *(float4*)&f[4] = *(const float4*)(wq + (size_t)oc*1024 + kc*64 + g*8 + 4);
        uint4 hi, lo; split8(f, hi, lo);
        g_wqkvP[gid*2]   = hi;
        g_wqkvP[gid*2+1] = lo;
    } else {                                 // w_proj: 256 oc x 512 k
        int gid2 = gid - 98304;
        if (gid2 >= 16384) return;
        int g = gid2 & 7, t = gid2 >> 3;
        int oc = t % 256, kc = t / 256;
        float f[8];
        *(float4*)&f[0] = *(const float4*)(wp + (size_t)oc*512 + kc*64 + g*8);
        *(float4*)&f[4] = *(const float4*)(wp + (size_t)oc*512 + kc*64 + g*8 + 4);
        uint4 hi, lo; split8(f, hi, lo);
        g_wprojP[gid2*2]   = hi;
        g_wprojP[gid2*2+1] = lo;
    }
}

// =========================================================================
// Kernel 0b: convert x -> im2col-packed fp16: g_xP[b][ci][pix] = patch(4)
// =========================================================================
__global__ __launch_bounds__(256) void cvt_x_kernel(const float* __restrict__ x)
{
    int gid = blockIdx.x * 256 + threadIdx.x;    // (b*256+ci)*4096 + pix
    int pix = gid & 4095, bc = gid >> 12;
    int oh = pix >> 6, ow = pix & 63;
    const float* p = x + (size_t)bc * 16384 + oh * 256 + ow * 2;
    float2 r0 = *(const float2*)p;
    float2 r1 = *(const float2*)(p + 128);
    __half2 a = __floats2half2_rn(r0.x, r0.y);
    __half2 b = __floats2half2_rn(r1.x, r1.y);
    uint2 o;
    o.x = *(uint32_t*)&a;
    o.y = *(uint32_t*)&b;
    g_xP[gid] = o;
}

// =========================================================================
// Kernel 1: patchify conv (2x2 s2) + BN via mma.sync fp16 (split-A, plain-B)
//   M=768(oc) N=65536(pix) K=1024. CTA 128x128, 8 warps (4M x 2N).
// =========================================================================
__global__ __launch_bounds__(256, 2)
void conv_mma_kernel(const float* __restrict__ gamma, const float* __restrict__ beta)
{
    extern __shared__ char sm[];
    const uint32_t sb = smem_u32(sm);
    const int tid = threadIdx.x, lane = tid & 31, wid = tid >> 5;
    const int wm = wid >> 1, wn = wid & 1;

    const int m0   = blockIdx.x * 128;
    const int p0   = blockIdx.y * 128;
    const int b    = p0 >> 12;
    const int pixb = p0 & 4095;

    const uint32_t aAddr = sb + OFF_AH +
        (uint32_t)((wm*32 + (lane & 15)) * RB + ((lane >> 4) & 1) * 16);
    const uint32_t bAddr = sb + OFF_BH +
        (uint32_t)((wn*64 + ((lane >> 4) & 1) * 8 + (lane & 7)) * RB +
                   ((lane >> 3) & 1) * 16);

    // A loader decode (8 uint4/thread/chunk, fully coalesced)
    const int isLo = tid & 1;
    const int gA   = (tid >> 1) & 7;
    const int oc0  = tid >> 4;                 // 0..15
    const uint32_t aDstBase = (isLo ? OFF_AL : OFF_AH) + gA * 16;
    // B loader: 128 threads x 16 ci halves
    const int pixL = tid & 127, ciH = tid >> 7;
    const int pixG = pixb + pixL;
    const uint2* xsrc = g_xP + (size_t)b * 256 * 4096;

    float acc[2][8][4];
#pragma unroll
    for (int i = 0; i < 2; i++)
#pragma unroll
        for (int j = 0; j < 8; j++)
#pragma unroll
            for (int q = 0; q < 4; q++) acc[i][j][q] = 0.0f;

    for (int c = 0; c < 16; ++c) {
        // ---- A tile (pre-split fp16 hi/lo) ----
        const uint4* wsrc = g_wqkvP + ((size_t)c*768 + m0) * 16;  // *8 groups *2
#pragma unroll
        for (int i = 0; i < 8; ++i) {
            int oc = oc0 + i * 16;
            uint4 v = wsrc[(oc * 8 + gA) * 2 + isLo];
            *(uint4*)(sm + aDstBase + oc * RB) = v;
        }
        // ---- B tile (pre-converted fp16 patches, contiguous) ----
#pragma unroll
        for (int cj = 0; cj < 8; ++cj) {
            int ciL = ciH * 8 + cj;
            uint2 v = xsrc[(size_t)(16*c + ciL) * 4096 + pixG];
            *(uint2*)(sm + OFF_BH + pixL * RB + ciL * 8) = v;
        }
        __syncthreads();

        // ---- MMA: 4 ksteps, (Ah + Al) x Bh ----
#pragma unroll
        for (int ks = 0; ks < 4; ++ks) {
            uint32_t ah[2][4], al[2][4];
            ldsm4(aAddr + ks*32,            ah[0]);
            ldsm4(aAddr + 16*RB + ks*32,    ah[1]);
            ldsm4(aAddr + (OFF_AL-OFF_AH) + ks*32,         al[0]);
            ldsm4(aAddr + (OFF_AL-OFF_AH) + 16*RB + ks*32, al[1]);
#pragma unroll
            for (int pr = 0; pr < 4; ++pr) {
                uint32_t bh[4];
                ldsm4(bAddr + pr*16*RB + ks*32, bh);
#pragma unroll
                for (int mf = 0; mf < 2; ++mf) {
                    mma16816(acc[mf][2*pr],   ah[mf], bh[0], bh[1]);
                    mma16816(acc[mf][2*pr+1], ah[mf], bh[2], bh[3]);
                    mma16816(acc[mf][2*pr],   al[mf], bh[0], bh[1]);
                    mma16816(acc[mf][2*pr+1], al[mf], bh[2], bh[3]);
                }
            }
        }
        __syncthreads();
    }

    // ---- epilogue: BN -> g_qkv ----
    const int quad = lane >> 2, qc = (lane & 3) * 2;
#pragma unroll
    for (int mf = 0; mf < 2; ++mf)
#pragma unroll
        for (int h = 0; h < 2; ++h) {
            int oc = m0 + wm*32 + mf*16 + h*8 + quad;
            float sc = gamma[oc] * rsqrtf(1.0f + BN_EPS);
            float bt = beta[oc];
            float* orow = g_qkv + ((size_t)b * 768 + oc) * 4096 + pixb + wn*64 + qc;
#pragma unroll
            for (int nf = 0; nf < 8; ++nf) {
                float2 o;
                o.x = acc[mf][nf][2*h]     * sc + bt;
                o.y = acc[mf][nf][2*h + 1] * sc + bt;
                *(float2*)(orow + nf*8) = o;
            }
        }
}

// =========================================================================
// Kernel 2: 64x64 plane transpose  g_qkv -> g_qkvT (12288 planes)
// =========================================================================
__global__ __launch_bounds__(256) void transpose_kernel()
{
    const size_t zoff = (size_t)blockIdx.z * 4096u;
    const float* src = g_qkv  + zoff;
    float*       dst = g_qkvT + zoff;

    __shared__ float tile[32][33];
    const int x0 = blockIdx.x * 32;
    const int y0 = blockIdx.y * 32;
    const int tx = threadIdx.x & 31;
    const int ty = threadIdx.x >> 5;

#pragma unroll
    for (int i = 0; i < 32; i += 8)
        tile[ty + i][tx] = src[(y0 + ty + i) * 64 + x0 + tx];
    __syncthreads();
#pragma unroll
    for (int i = 0; i < 32; i += 8)
        dst[(x0 + ty + i) * 64 + y0 + tx] = tile[tx][ty + i];
}

// =========================================================================
// Kernel 3/4: axial attention, one (b, row) per block, 256 threads.
//   Output: fp16 into g_vP[b][pix][512] (pass0 -> ch 0..255, pass1 -> 256..511)
// =========================================================================
#define ATTN_SMEM_FLOATS (64*68 + 64*260 + 512)

__global__ __launch_bounds__(256) void attn_kernel(int pass)
{
    extern __shared__ float asmem[];
    float* Ssm = asmem;               // 64*68
    float* VT  = asmem + 64 * 68;     // 64*260  (stage C)
    float* red = asmem + 64*68 + 64*260;  // 512 floats (softmax reduce)
    float* Ks  = VT;                  // 16*64   (stage A, aliased)
    float* Qs  = VT + 16 * 64;        // 16*64

    const int r   = blockIdx.x;   // h (pass0) or w (pass1)
    const int b   = blockIdx.y;
    const int tid = threadIdx.x;

    const float* src = (pass == 0) ? g_qkv : g_qkvT;
    __half* dstP = g_vP + (size_t)b * 4096u * 512u + pass * 256;

    const float* Qp = src + ((size_t)b * 768 +   0) * 4096 + r * 64;
    const float* Kp = src + ((size_t)b * 768 + 256) * 4096 + r * 64;
    const float* Vp = src + ((size_t)b * 768 + 512) * 4096 + r * 64;

    // ---------------- stage A: S = scale * K^T Q ----------------
    const int ti = tid >> 4;
    const int tj = tid & 15;
    float sacc[4][4];
#pragma unroll
    for (int i = 0; i < 4; i++)
#pragma unroll
        for (int j = 0; j < 4; j++) sacc[i][j] = 0.0f;

    const int crow = tid >> 4;
    const int col4 = tid & 15;

    for (int c0 = 0; c0 < 256; c0 += 16) {
        *(float4*)&Ks[crow * 64 + col4 * 4] =
            *(const float4*)&Kp[(size_t)(c0 + crow) * 4096 + col4 * 4];
        *(float4*)&Qs[crow * 64 + col4 * 4] =
            *(const float4*)&Qp[(size_t)(c0 + crow) * 4096 + col4 * 4];
        __syncthreads();
#pragma unroll
        for (int cc = 0; cc < 16; cc++) {
            float a[4], q[4];
            *(float4*)a = *(const float4*)&Ks[cc * 64 + ti * 4];
            *(float4*)q = *(const float4*)&Qs[cc * 64 + tj * 4];
#pragma unroll
            for (int i = 0; i < 4; i++)
#pragma unroll
                for (int j = 0; j < 4; j++) sacc[i][j] += a[i] * q[j];
        }
        __syncthreads();
    }
#pragma unroll
    for (int i = 0; i < 4; i++) {
        float4 v;
        v.x = sacc[i][0] * ATTN_SCALE; v.y = sacc[i][1] * ATTN_SCALE;
        v.z = sacc[i][2] * ATTN_SCALE; v.w = sacc[i][3] * ATTN_SCALE;
        *(float4*)&Ssm[(ti * 4 + i) * 68 + tj * 4] = v;
    }
    __syncthreads();

    // ---------------- stage C prologue: stage V transposed into smem ------
#pragma unroll
    for (int it = 0; it < 16; it++) {
        int idx = it * 256 + tid;
        int i4  = (idx & 3) | (((idx >> 8) & 3) << 2);
        int c   = ((idx >> 2) & 63) | ((idx >> 10) << 6);
        const float4 v = *(const float4*)&Vp[(size_t)c * 4096 + i4 * 4];
        VT[(i4 * 4 + 0) * 260 + c] = v.x;
        VT[(i4 * 4 + 1) * 260 + c] = v.y;
        VT[(i4 * 4 + 2) * 260 + c] = v.z;
        VT[(i4 * 4 + 3) * 260 + c] = v.w;
    }

    // ------- stage B: column softmax over i (256 threads: 4 quarters) -----
    {
        const int j  = tid & 63;
        const int q  = tid >> 6;
        const int i0 = q * 16;
        float m = -1e30f;
#pragma unroll 4
        for (int i = 0; i < 16; i++) m = fmaxf(m, Ssm[(i0+i) * 68 + j]);
        red[q*64 + j] = m;
        __syncthreads();
        m = fmaxf(fmaxf(red[j], red[64+j]), fmaxf(red[128+j], red[192+j]));
        float s = 0.0f;
#pragma unroll 4
        for (int i = 0; i < 16; i++) {
            float e = expf(Ssm[(i0+i) * 68 + j] - m);
            s += e;
            Ssm[(i0+i) * 68 + j] = e;
        }
        red[256 + q*64 + j] = s;
        __syncthreads();
        float inv = 1.0f / (red[256+j] + red[320+j] + red[384+j] + red[448+j]);
#pragma unroll 4
        for (int i = 0; i < 16; i++) Ssm[(i0+i) * 68 + j] *= inv;
    }
    __syncthreads();

    // ---------------- stage C: O = V * P ----------------
    const int c0 = (tid >> 3) * 8;   // 0..248
    const int j0 = (tid & 7) * 8;    // 0..56
    float oacc[8][8];
#pragma unroll
    for (int i = 0; i < 8; i++)
#pragma unroll
        for (int j = 0; j < 8; j++) oacc[i][j] = 0.0f;

#pragma unroll 4
    for (int i = 0; i < 64; i++) {
        float a[8], pb[8];
        *(float4*)&a[0]  = *(const float4*)&VT[i * 260 + c0];
        *(float4*)&a[4]  = *(const float4*)&VT[i * 260 + c0 + 4];
        *(float4*)&pb[0] = *(const float4*)&Ssm[i * 68 + j0];
        *(float4*)&pb[4] = *(const float4*)&Ssm[i * 68 + j0 + 4];
#pragma unroll
        for (int ci = 0; ci < 8; ci++)
#pragma unroll
            for (int j = 0; j < 8; j++) oacc[ci][j] += a[ci] * pb[j];
    }

    // fp16 pixel-major writes: [pix][ch]
#pragma unroll
    for (int j = 0; j < 8; j++) {
        int jj  = j0 + j;
        int pix = (pass == 0) ? (r * 64 + jj) : (jj * 64 + r);
        __half2 p0 = __floats2half2_rn(oacc[0][j], oacc[1][j]);
        __half2 p1 = __floats2half2_rn(oacc[2][j], oacc[3][j]);
        __half2 p2 = __floats2half2_rn(oacc[4][j], oacc[5][j]);
        __half2 p3 = __floats2half2_rn(oacc[6][j], oacc[7][j]);
        uint4 st = make_uint4(*(uint32_t*)&p0, *(uint32_t*)&p1,
                              *(uint32_t*)&p2, *(uint32_t*)&p3);
        *(uint4*)(dstP + (size_t)pix * 512 + c0) = st;
    }
}

// =========================================================================
// Kernel 5: 1x1 proj + BN2 + ReLU via mma.sync fp16 (split-A, plain-B)
//   M=256(oc) N=65536(pix) K=512 from g_vP. grid=(2,512).
// =========================================================================
__global__ __launch_bounds__(256, 2)
void proj_mma_kernel(const float* __restrict__ gamma,
                     const float* __restrict__ beta,
                     float* __restrict__ out)
{
    extern __shared__ char sm[];
    const uint32_t sb = smem_u32(sm);
    const int tid = threadIdx.x, lane = tid & 31, wid = tid >> 5;
    const int wm = wid >> 1, wn = wid & 1;

    const int m0   = blockIdx.x * 128;
    const int p0   = blockIdx.y * 128;
    const int b    = p0 >> 12;
    const int pixb = p0 & 4095;

    const uint32_t aAddr = sb + OFF_AH +
        (uint32_t)((wm*32 + (lane & 15)) * RB + ((lane >> 4) & 1) * 16);
    const uint32_t bAddr = sb + OFF_BH +
        (uint32_t)((wn*64 + ((lane >> 4) & 1) * 8 + (lane & 7)) * RB +
                   ((lane >> 3) & 1) * 16);

    const int isLo = tid & 1;
    const int gA   = (tid >> 1) & 7;
    const int oc0  = tid >> 4;
    const uint32_t aDstBase = (isLo ? OFF_AL : OFF_AH) + gA * 16;
    const int prow = tid >> 4;          // 0..15
    const int pcol = tid & 15;
    const __half* vbase = g_vP + ((size_t)(b * 4096) + pixb) * 512;

    float acc[2][8][4];
#pragma unroll
    for (int i = 0; i < 2; i++)
#pragma unroll
        for (int j = 0; j < 8; j++)
#pragma unroll
            for (int q = 0; q < 4; q++) acc[i][j][q] = 0.0f;

    for (int c = 0; c < 8; ++c) {
        // ---- A tile ----
        const uint4* wsrc = g_wprojP + ((size_t)c*256 + m0) * 16;
#pragma unroll
        for (int i = 0; i < 8; ++i) {
            int oc = oc0 + i * 16;
            uint4 v = wsrc[(oc * 8 + gA) * 2 + isLo];
            *(uint4*)(sm + aDstBase + oc * RB) = v;
        }
        // ---- B tile: fp16 pixel rows, contiguous k ----
#pragma unroll
        for (int rep = 0; rep < 8; ++rep) {
            int pix = rep * 16 + prow;
            uint2 v = *(const uint2*)(vbase + (size_t)pix * 512 + 64*c + pcol*4);
            *(uint2*)(sm + OFF_BH + pix * RB + pcol * 8) = v;
        }
        __syncthreads();

#pragma unroll
        for (int ks = 0; ks < 4; ++ks) {
            uint32_t ah[2][4], al[2][4];
            ldsm4(aAddr + ks*32,            ah[0]);
            ldsm4(aAddr + 16*RB + ks*32,    ah[1]);
            ldsm4(aAddr + (OFF_AL-OFF_AH) + ks*32,         al[0]);
            ldsm4(aAddr + (OFF_AL-OFF_AH) + 16*RB + ks*32, al[1]);
#pragma unroll
            for (int pr = 0; pr < 4; ++pr) {
                uint32_t bh[4];
                ldsm4(bAddr + pr*16*RB + ks*32, bh);
#pragma unroll
                for (int mf = 0; mf < 2; ++mf) {
                    mma16816(acc[mf][2*pr],   ah[mf], bh[0], bh[1]);
                    mma16816(acc[mf][2*pr+1], ah[mf], bh[2], bh[3]);
                    mma16816(acc[mf][2*pr],   al[mf], bh[0], bh[1]);
                    mma16816(acc[mf][2*pr+1], al[mf], bh[2], bh[3]);
                }
            }
        }
        __syncthreads();
    }

    // ---- epilogue: BN2 + ReLU -> out ----
    const int quad = lane >> 2, qc = (lane & 3) * 2;
#pragma unroll
    for (int mf = 0; mf < 2; ++mf)
#pragma unroll
        for (int h = 0; h < 2; ++h) {
            int oc = m0 + wm*32 + mf*16 + h*8 + quad;
            float sc = gamma[oc] * rsqrtf(1.0f + BN_EPS);
            float bt = beta[oc];
            float* orow = out + ((size_t)b * 256 + oc) * 4096 + pixb + wn*64 + qc;
#pragma unroll
            for (int nf = 0; nf < 8; ++nf) {
                float2 o;
                o.x = fmaxf(acc[mf][nf][2*h]     * sc + bt, 0.0f);
                o.y = fmaxf(acc[mf][nf][2*h + 1] * sc + bt, 0.0f);
                *(float2*)(orow + nf*8) = o;
            }
        }
}

// =========================================================================
extern "C" void kernel_launch(void* const* d_in, const int* in_sizes, int n_in,
                              void* d_out, int out_size)
{
    const float* x      = (const float*)d_in[0];
    const float* w_qkv  = (const float*)d_in[1];
    const float* gamma1 = (const float*)d_in[2];
    const float* beta1  = (const float*)d_in[3];
    const float* w_proj = (const float*)d_in[4];
    const float* gamma2 = (const float*)d_in[5];
    const float* beta2  = (const float*)d_in[6];
    float* out = (float*)d_out;

    const int attn_smem = ATTN_SMEM_FLOATS * (int)sizeof(float);  // 86016 B
    cudaFuncSetAttribute((const void*)attn_kernel,
                         cudaFuncAttributeMaxDynamicSharedMemorySize, attn_smem);
    cudaFuncSetAttribute((const void*)conv_mma_kernel,
                         cudaFuncAttributeMaxDynamicSharedMemorySize, GEMM_SMEM);
    cudaFuncSetAttribute((const void*)proj_mma_kernel,
                         cudaFuncAttributeMaxDynamicSharedMemorySize, GEMM_SMEM);

    // 0. pre-convert operands to fp16 (hi/lo split for weights)
    cvt_w_kernel<<<448, 256>>>(w_qkv, w_proj);
    cvt_x_kernel<<<65536, 256>>>(x);
    // 1. patchify conv + BN1 (fp16 mma.sync) -> g_qkv
    conv_mma_kernel<<<dim3(6, 512), 256, GEMM_SMEM>>>(gamma1, beta1);
    // 2. transpose q|k|v planes -> g_qkvT
    transpose_kernel<<<dim3(2, 2, 16 * 768), 256>>>();
    // 3. height-axis attention -> g_vP[:, :, 0:256]
    attn_kernel<<<dim3(64, 16), 256, attn_smem>>>(0);
    // 4. width-axis attention  -> g_vP[:, :, 256:512]
    attn_kernel<<<dim3(64, 16), 256, attn_smem>>>(1);
    // 5. 1x1 proj + BN2 + ReLU (fp16 mma.sync) -> out
    proj_mma_kernel<<<dim3(2, 512), 256, GEMM_SMEM>>>(gamma2, beta2, out);
}

// round 16
// speedup vs baseline: 1.0066x; 1.0066x over previous
#include <cuda_runtime.h>
#include <cuda_fp16.h>
#include <math.h>
#include <stdint.h>

#define BN_EPS 1e-5f
#define ATTN_SCALE 0.0625f   // 1/sqrt(256)

// ---------------- scratch (device globals; no allocation) ----------------
__device__ float  g_qkv  [16u*768u*4096u];     // [b,768,h,w]  (q|k|v) fp32
__device__ float  g_qkvT [16u*768u*4096u];     // [b,768,w,h]  fp32
__device__ __half g_vP   [16u*4096u*512u];     // [b,pix,512]  (vh|vw) fp16
__device__ uint2  g_xP   [16u*256u*4096u];     // [b,ci,pix] -> 4 fp16 (khw patch)
__device__ uint4  g_wqkvP[196608u];            // [(kc*768+oc)*8+g]*2 + {hi,lo}
__device__ uint4  g_wprojP[32768u];            // [(kc*256+oc)*8+g]*2 + {hi,lo}

// ======================= warp-MMA helpers (base-ISA only) =================
__device__ __forceinline__ uint32_t smem_u32(const void* p) {
    uint32_t a;
    asm("{ .reg .u64 t; cvta.to.shared.u64 t, %1; cvt.u32.u64 %0, t; }"
        : "=r"(a) : "l"(p));
    return a;
}

__device__ __forceinline__ void ldsm4(uint32_t addr, uint32_t* r) {
    asm volatile("ldmatrix.sync.aligned.m8n8.x4.shared.b16 {%0,%1,%2,%3}, [%4];"
        : "=r"(r[0]), "=r"(r[1]), "=r"(r[2]), "=r"(r[3]) : "r"(addr));
}

__device__ __forceinline__ void mma16816(float* c, const uint32_t* a,
                                         uint32_t b0, uint32_t b1) {
    asm volatile(
        "mma.sync.aligned.m16n8k16.row.col.f32.f16.f16.f32 "
        "{%0,%1,%2,%3}, {%4,%5,%6,%7}, {%8,%9}, {%0,%1,%2,%3};"
        : "+f"(c[0]), "+f"(c[1]), "+f"(c[2]), "+f"(c[3])
        : "r"(a[0]), "r"(a[1]), "r"(a[2]), "r"(a[3]), "r"(b0), "r"(b1));
}

// 8 consecutive floats -> fp16 hi uint4 + fp16 lo (residual) uint4
__device__ __forceinline__ void split8(const float* f, uint4& hi, uint4& lo) {
    uint32_t h[4], l[4];
#pragma unroll
    for (int j = 0; j < 4; ++j) {
        __half2 hh = __floats2half2_rn(f[2*j], f[2*j+1]);
        float ra = f[2*j]   - __low2float(hh);
        float rb = f[2*j+1] - __high2float(hh);
        __half2 ll = __floats2half2_rn(ra, rb);
        h[j] = *(uint32_t*)&hh;
        l[j] = *(uint32_t*)&ll;
    }
    hi = make_uint4(h[0], h[1], h[2], h[3]);
    lo = make_uint4(l[0], l[1], l[2], l[3]);
}

// smem layout for GEMM kernels (K-chunk = 64 fp16, rows padded to 144B)
#define RB      144
#define OFF_AH  0
#define OFF_AL  18432
#define OFF_BH  36864
#define GEMM_SMEM 55296

// =========================================================================
// Kernel 0a: convert weights -> packed fp16 hi/lo, chunk-major
// =========================================================================
__global__ __launch_bounds__(256) void cvt_w_kernel(
    const float* __restrict__ wq, const float* __restrict__ wp)
{
    int gid = blockIdx.x * 256 + threadIdx.x;
    if (gid < 98304) {                       // w_qkv: 768 oc x 1024 k
        int g = gid & 7, t = gid >> 3;
        int oc = t % 768, kc = t / 768;
        float f[8];
        *(float4*)&f[0] = *(const float4*)(wq + (size_t)oc*1024 + kc*64 + g*8);
        *(float4*)&f[4] = *(const float4*)(wq + (size_t)oc*1024 + kc*64 + g*8 + 4);
        uint4 hi, lo; split8(f, hi, lo);
        g_wqkvP[gid*2]   = hi;
        g_wqkvP[gid*2+1] = lo;
    } else {                                 // w_proj: 256 oc x 512 k
        int gid2 = gid - 98304;
        if (gid2 >= 16384) return;
        int g = gid2 & 7, t = gid2 >> 3;
        int oc = t % 256, kc = t / 256;
        float f[8];
        *(float4*)&f[0] = *(const float4*)(wp + (size_t)oc*512 + kc*64 + g*8);
        *(float4*)&f[4] = *(const float4*)(wp + (size_t)oc*512 + kc*64 + g*8 + 4);
        uint4 hi, lo; split8(f, hi, lo);
        g_wprojP[gid2*2]   = hi;
        g_wprojP[gid2*2+1] = lo;
    }
}

// =========================================================================
// Kernel 0b: convert x -> im2col-packed fp16: g_xP[b][ci][pix] = patch(4)
// =========================================================================
__global__ __launch_bounds__(256) void cvt_x_kernel(const float* __restrict__ x)
{
    int gid = blockIdx.x * 256 + threadIdx.x;    // (b*256+ci)*4096 + pix
    int pix = gid & 4095, bc = gid >> 12;
    int oh = pix >> 6, ow = pix & 63;
    const float* p = x + (size_t)bc * 16384 + oh * 256 + ow * 2;
    float2 r0 = *(const float2*)p;
    float2 r1 = *(const float2*)(p + 128);
    __half2 a = __floats2half2_rn(r0.x, r0.y);
    __half2 b = __floats2half2_rn(r1.x, r1.y);
    uint2 o;
    o.x = *(uint32_t*)&a;
    o.y = *(uint32_t*)&b;
    g_xP[gid] = o;
}

// =========================================================================
// Kernel 1: patchify conv (2x2 s2) + BN via mma.sync fp16 (split-A, plain-B)
//   M=768(oc) N=65536(pix) K=1024. CTA 128x128, 8 warps (4M x 2N).
// =========================================================================
__global__ __launch_bounds__(256, 2)
void conv_mma_kernel(const float* __restrict__ gamma, const float* __restrict__ beta)
{
    extern __shared__ char sm[];
    const uint32_t sb = smem_u32(sm);
    const int tid = threadIdx.x, lane = tid & 31, wid = tid >> 5;
    const int wm = wid >> 1, wn = wid & 1;

    const int m0   = blockIdx.x * 128;
    const int p0   = blockIdx.y * 128;
    const int b    = p0 >> 12;
    const int pixb = p0 & 4095;

    const uint32_t aAddr = sb + OFF_AH +
        (uint32_t)((wm*32 + (lane & 15)) * RB + ((lane >> 4) & 1) * 16);
    const uint32_t bAddr = sb + OFF_BH +
        (uint32_t)((wn*64 + ((lane >> 4) & 1) * 8 + (lane & 7)) * RB +
                   ((lane >> 3) & 1) * 16);

    // A loader decode (8 uint4/thread/chunk, fully coalesced)
    const int isLo = tid & 1;
    const int gA   = (tid >> 1) & 7;
    const int oc0  = tid >> 4;                 // 0..15
    const uint32_t aDstBase = (isLo ? OFF_AL : OFF_AH) + gA * 16;
    // B loader: 128 threads x 16 ci halves
    const int pixL = tid & 127, ciH = tid >> 7;
    const int pixG = pixb + pixL;
    const uint2* xsrc = g_xP + (size_t)b * 256 * 4096;

    float acc[2][8][4];
#pragma unroll
    for (int i = 0; i < 2; i++)
#pragma unroll
        for (int j = 0; j < 8; j++)
#pragma unroll
            for (int q = 0; q < 4; q++) acc[i][j][q] = 0.0f;

    for (int c = 0; c < 16; ++c) {
        // ---- A tile (pre-split fp16 hi/lo) ----
        const uint4* wsrc = g_wqkvP + ((size_t)c*768 + m0) * 16;  // *8 groups *2
#pragma unroll
        for (int i = 0; i < 8; ++i) {
            int oc = oc0 + i * 16;
            uint4 v = wsrc[(oc * 8 + gA) * 2 + isLo];
            *(uint4*)(sm + aDstBase + oc * RB) = v;
        }
        // ---- B tile (pre-converted fp16 patches, contiguous) ----
#pragma unroll
        for (int cj = 0; cj < 8; ++cj) {
            int ciL = ciH * 8 + cj;
            uint2 v = xsrc[(size_t)(16*c + ciL) * 4096 + pixG];
            *(uint2*)(sm + OFF_BH + pixL * RB + ciL * 8) = v;
        }
        __syncthreads();

        // ---- MMA: 4 ksteps, (Ah + Al) x Bh ----
#pragma unroll
        for (int ks = 0; ks < 4; ++ks) {
            uint32_t ah[2][4], al[2][4];
            ldsm4(aAddr + ks*32,            ah[0]);
            ldsm4(aAddr + 16*RB + ks*32,    ah[1]);
            ldsm4(aAddr + (OFF_AL-OFF_AH) + ks*32,         al[0]);
            ldsm4(aAddr + (OFF_AL-OFF_AH) + 16*RB + ks*32, al[1]);
#pragma unroll
            for (int pr = 0; pr < 4; ++pr) {
                uint32_t bh[4];
                ldsm4(bAddr + pr*16*RB + ks*32, bh);
#pragma unroll
                for (int mf = 0; mf < 2; ++mf) {
                    mma16816(acc[mf][2*pr],   ah[mf], bh[0], bh[1]);
                    mma16816(acc[mf][2*pr+1], ah[mf], bh[2], bh[3]);
                    mma16816(acc[mf][2*pr],   al[mf], bh[0], bh[1]);
                    mma16816(acc[mf][2*pr+1], al[mf], bh[2], bh[3]);
                }
            }
        }
        __syncthreads();
    }

    // ---- epilogue: BN -> g_qkv ----
    const int quad = lane >> 2, qc = (lane & 3) * 2;
#pragma unroll
    for (int mf = 0; mf < 2; ++mf)
#pragma unroll
        for (int h = 0; h < 2; ++h) {
            int oc = m0 + wm*32 + mf*16 + h*8 + quad;
            float sc = gamma[oc] * rsqrtf(1.0f + BN_EPS);
            float bt = beta[oc];
            float* orow = g_qkv + ((size_t)b * 768 + oc) * 4096 + pixb + wn*64 + qc;
#pragma unroll
            for (int nf = 0; nf < 8; ++nf) {
                float2 o;
                o.x = acc[mf][nf][2*h]     * sc + bt;
                o.y = acc[mf][nf][2*h + 1] * sc + bt;
                *(float2*)(orow + nf*8) = o;
            }
        }
}

// =========================================================================
// Kernel 2: 64x64 plane transpose  g_qkv -> g_qkvT (12288 planes)
// =========================================================================
__global__ __launch_bounds__(256) void transpose_kernel()
{
    const size_t zoff = (size_t)blockIdx.z * 4096u;
    const float* src = g_qkv  + zoff;
    float*       dst = g_qkvT + zoff;

    __shared__ float tile[32][33];
    const int x0 = blockIdx.x * 32;
    const int y0 = blockIdx.y * 32;
    const int tx = threadIdx.x & 31;
    const int ty = threadIdx.x >> 5;

#pragma unroll
    for (int i = 0; i < 32; i += 8)
        tile[ty + i][tx] = src[(y0 + ty + i) * 64 + x0 + tx];
    __syncthreads();
#pragma unroll
    for (int i = 0; i < 32; i += 8)
        dst[(x0 + ty + i) * 64 + y0 + tx] = tile[tx][ty + i];
}

// =========================================================================
// Kernel 3/4: axial attention, one (b, row) per block, 256 threads.
//   Output: fp16 into g_vP[b][pix][512] (pass0 -> ch 0..255, pass1 -> 256..511)
// =========================================================================
#define ATTN_SMEM_FLOATS (64*68 + 64*260 + 512)

__global__ __launch_bounds__(256) void attn_kernel(int pass)
{
    extern __shared__ float asmem[];
    float* Ssm = asmem;               // 64*68
    float* VT  = asmem + 64 * 68;     // 64*260  (stage C)
    float* red = asmem + 64*68 + 64*260;  // 512 floats (softmax reduce)
    float* Ks  = VT;                  // 16*64   (stage A, aliased)
    float* Qs  = VT + 16 * 64;        // 16*64

    const int r   = blockIdx.x;   // h (pass0) or w (pass1)
    const int b   = blockIdx.y;
    const int tid = threadIdx.x;

    const float* src = (pass == 0) ? g_qkv : g_qkvT;
    __half* dstP = g_vP + (size_t)b * 4096u * 512u + pass * 256;

    const float* Qp = src + ((size_t)b * 768 +   0) * 4096 + r * 64;
    const float* Kp = src + ((size_t)b * 768 + 256) * 4096 + r * 64;
    const float* Vp = src + ((size_t)b * 768 + 512) * 4096 + r * 64;

    // ---------------- stage A: S = scale * K^T Q ----------------
    const int ti = tid >> 4;
    const int tj = tid & 15;
    float sacc[4][4];
#pragma unroll
    for (int i = 0; i < 4; i++)
#pragma unroll
        for (int j = 0; j < 4; j++) sacc[i][j] = 0.0f;

    const int crow = tid >> 4;
    const int col4 = tid & 15;

    for (int c0 = 0; c0 < 256; c0 += 16) {
        *(float4*)&Ks[crow * 64 + col4 * 4] =
            *(const float4*)&Kp[(size_t)(c0 + crow) * 4096 + col4 * 4];
        *(float4*)&Qs[crow * 64 + col4 * 4] =
            *(const float4*)&Qp[(size_t)(c0 + crow) * 4096 + col4 * 4];
        __syncthreads();
#pragma unroll
        for (int cc = 0; cc < 16; cc++) {
            float a[4], q[4];
            *(float4*)a = *(const float4*)&Ks[cc * 64 + ti * 4];
            *(float4*)q = *(const float4*)&Qs[cc * 64 + tj * 4];
#pragma unroll
            for (int i = 0; i < 4; i++)
#pragma unroll
                for (int j = 0; j < 4; j++) sacc[i][j] += a[i] * q[j];
        }
        __syncthreads();
    }
#pragma unroll
    for (int i = 0; i < 4; i++) {
        float4 v;
        v.x = sacc[i][0] * ATTN_SCALE; v.y = sacc[i][1] * ATTN_SCALE;
        v.z = sacc[i][2] * ATTN_SCALE; v.w = sacc[i][3] * ATTN_SCALE;
        *(float4*)&Ssm[(ti * 4 + i) * 68 + tj * 4] = v;
    }
    __syncthreads();

    // ---------------- stage C prologue: stage V transposed into smem ------
#pragma unroll
    for (int it = 0; it < 16; it++) {
        int idx = it * 256 + tid;
        int i4  = (idx & 3) | (((idx >> 8) & 3) << 2);
        int c   = ((idx >> 2) & 63) | ((idx >> 10) << 6);
        const float4 v = *(const float4*)&Vp[(size_t)c * 4096 + i4 * 4];
        VT[(i4 * 4 + 0) * 260 + c] = v.x;
        VT[(i4 * 4 + 1) * 260 + c] = v.y;
        VT[(i4 * 4 + 2) * 260 + c] = v.z;
        VT[(i4 * 4 + 3) * 260 + c] = v.w;
    }

    // ------- stage B: column softmax over i (256 threads: 4 quarters) -----
    {
        const int j  = tid & 63;
        const int q  = tid >> 6;
        const int i0 = q * 16;
        float m = -1e30f;
#pragma unroll 4
        for (int i = 0; i < 16; i++) m = fmaxf(m, Ssm[(i0+i) * 68 + j]);
        red[q*64 + j] = m;
        __syncthreads();
        m = fmaxf(fmaxf(red[j], red[64+j]), fmaxf(red[128+j], red[192+j]));
        float s = 0.0f;
#pragma unroll 4
        for (int i = 0; i < 16; i++) {
            float e = expf(Ssm[(i0+i) * 68 + j] - m);
            s += e;
            Ssm[(i0+i) * 68 + j] = e;
        }
        red[256 + q*64 + j] = s;
        __syncthreads();
        float inv = 1.0f / (red[256+j] + red[320+j] + red[384+j] + red[448+j]);
#pragma unroll 4
        for (int i = 0; i < 16; i++) Ssm[(i0+i) * 68 + j] *= inv;
    }
    __syncthreads();

    // ---------------- stage C: O = V * P ----------------
    const int c0 = (tid >> 3) * 8;   // 0..248
    const int j0 = (tid & 7) * 8;    // 0..56
    float oacc[8][8];
#pragma unroll
    for (int i = 0; i < 8; i++)
#pragma unroll
        for (int j = 0; j < 8; j++) oacc[i][j] = 0.0f;

#pragma unroll 4
    for (int i = 0; i < 64; i++) {
        float a[8], pb[8];
        *(float4*)&a[0]  = *(const float4*)&VT[i * 260 + c0];
        *(float4*)&a[4]  = *(const float4*)&VT[i * 260 + c0 + 4];
        *(float4*)&pb[0] = *(const float4*)&Ssm[i * 68 + j0];
        *(float4*)&pb[4] = *(const float4*)&Ssm[i * 68 + j0 + 4];
#pragma unroll
        for (int ci = 0; ci < 8; ci++)
#pragma unroll
            for (int j = 0; j < 8; j++) oacc[ci][j] += a[ci] * pb[j];
    }

    // fp16 pixel-major writes: [pix][ch]
#pragma unroll
    for (int j = 0; j < 8; j++) {
        int jj  = j0 + j;
        int pix = (pass == 0) ? (r * 64 + jj) : (jj * 64 + r);
        __half2 p0 = __floats2half2_rn(oacc[0][j], oacc[1][j]);
        __half2 p1 = __floats2half2_rn(oacc[2][j], oacc[3][j]);
        __half2 p2 = __floats2half2_rn(oacc[4][j], oacc[5][j]);
        __half2 p3 = __floats2half2_rn(oacc[6][j], oacc[7][j]);
        uint4 st = make_uint4(*(uint32_t*)&p0, *(uint32_t*)&p1,
                              *(uint32_t*)&p2, *(uint32_t*)&p3);
        *(uint4*)(dstP + (size_t)pix * 512 + c0) = st;
    }
}

// =========================================================================
// Kernel 5: 1x1 proj + BN2 + ReLU via mma.sync fp16 (split-A, plain-B)
//   M=256(oc) N=65536(pix) K=512 from g_vP. grid=(2,512).
// =========================================================================
__global__ __launch_bounds__(256, 2)
void proj_mma_kernel(const float* __restrict__ gamma,
                     const float* __restrict__ beta,
                     float* __restrict__ out)
{
    extern __shared__ char sm[];
    const uint32_t sb = smem_u32(sm);
    const int tid = threadIdx.x, lane = tid & 31, wid = tid >> 5;
    const int wm = wid >> 1, wn = wid & 1;

    const int m0   = blockIdx.x * 128;
    const int p0   = blockIdx.y * 128;
    const int b    = p0 >> 12;
    const int pixb = p0 & 4095;

    const uint32_t aAddr = sb + OFF_AH +
        (uint32_t)((wm*32 + (lane & 15)) * RB + ((lane >> 4) & 1) * 16);
    const uint32_t bAddr = sb + OFF_BH +
        (uint32_t)((wn*64 + ((lane >> 4) & 1) * 8 + (lane & 7)) * RB +
                   ((lane >> 3) & 1) * 16);

    const int isLo = tid & 1;
    const int gA   = (tid >> 1) & 7;
    const int oc0  = tid >> 4;
    const uint32_t aDstBase = (isLo ? OFF_AL : OFF_AH) + gA * 16;
    const int prow = tid >> 4;          // 0..15
    const int pcol = tid & 15;
    const __half* vbase = g_vP + ((size_t)(b * 4096) + pixb) * 512;

    float acc[2][8][4];
#pragma unroll
    for (int i = 0; i < 2; i++)
#pragma unroll
        for (int j = 0; j < 8; j++)
#pragma unroll
            for (int q = 0; q < 4; q++) acc[i][j][q] = 0.0f;

    for (int c = 0; c < 8; ++c) {
        // ---- A tile ----
        const uint4* wsrc = g_wprojP + ((size_t)c*256 + m0) * 16;
#pragma unroll
        for (int i = 0; i < 8; ++i) {
            int oc = oc0 + i * 16;
            uint4 v = wsrc[(oc * 8 + gA) * 2 + isLo];
            *(uint4*)(sm + aDstBase + oc * RB) = v;
        }
        // ---- B tile: fp16 pixel rows, contiguous k ----
#pragma unroll
        for (int rep = 0; rep < 8; ++rep) {
            int pix = rep * 16 + prow;
            uint2 v = *(const uint2*)(vbase + (size_t)pix * 512 + 64*c + pcol*4);
            *(uint2*)(sm + OFF_BH + pix * RB + pcol * 8) = v;
        }
        __syncthreads();

#pragma unroll
        for (int ks = 0; ks < 4; ++ks) {
            uint32_t ah[2][4], al[2][4];
            ldsm4(aAddr + ks*32,            ah[0]);
            ldsm4(aAddr + 16*RB + ks*32,    ah[1]);
            ldsm4(aAddr + (OFF_AL-OFF_AH) + ks*32,         al[0]);
            ldsm4(aAddr + (OFF_AL-OFF_AH) + 16*RB + ks*32, al[1]);
#pragma unroll
            for (int pr = 0; pr < 4; ++pr) {
                uint32_t bh[4];
                ldsm4(bAddr + pr*16*RB + ks*32, bh);
#pragma unroll
                for (int mf = 0; mf < 2; ++mf) {
                    mma16816(acc[mf][2*pr],   ah[mf], bh[0], bh[1]);
                    mma16816(acc[mf][2*pr+1], ah[mf], bh[2], bh[3]);
                    mma16816(acc[mf][2*pr],   al[mf], bh[0], bh[1]);
                    mma16816(acc[mf][2*pr+1], al[mf], bh[2], bh[3]);
                }
            }
        }
        __syncthreads();
    }

    // ---- epilogue: BN2 + ReLU -> out ----
    const int quad = lane >> 2, qc = (lane & 3) * 2;
#pragma unroll
    for (int mf = 0; mf < 2; ++mf)
#pragma unroll
        for (int h = 0; h < 2; ++h) {
            int oc = m0 + wm*32 + mf*16 + h*8 + quad;
            float sc = gamma[oc] * rsqrtf(1.0f + BN_EPS);
            float bt = beta[oc];
            float* orow = out + ((size_t)b * 256 + oc) * 4096 + pixb + wn*64 + qc;
#pragma unroll
            for (int nf = 0; nf < 8; ++nf) {
                float2 o;
                o.x = fmaxf(acc[mf][nf][2*h]     * sc + bt, 0.0f);
                o.y = fmaxf(acc[mf][nf][2*h + 1] * sc + bt, 0.0f);
                *(float2*)(orow + nf*8) = o;
            }
        }
}

// =========================================================================
extern "C" void kernel_launch(void* const* d_in, const int* in_sizes, int n_in,
                              void* d_out, int out_size)
{
    const float* x      = (const float*)d_in[0];
    const float* w_qkv  = (const float*)d_in[1];
    const float* gamma1 = (const float*)d_in[2];
    const float* beta1  = (const float*)d_in[3];
    const float* w_proj = (const float*)d_in[4];
    const float* gamma2 = (const float*)d_in[5];
    const float* beta2  = (const float*)d_in[6];
    float* out = (float*)d_out;

    const int attn_smem = ATTN_SMEM_FLOATS * (int)sizeof(float);  // 86016 B
    cudaFuncSetAttribute((const void*)attn_kernel,
                         cudaFuncAttributeMaxDynamicSharedMemorySize, attn_smem);
    cudaFuncSetAttribute((const void*)conv_mma_kernel,
                         cudaFuncAttributeMaxDynamicSharedMemorySize, GEMM_SMEM);
    cudaFuncSetAttribute((const void*)proj_mma_kernel,
                         cudaFuncAttributeMaxDynamicSharedMemorySize, GEMM_SMEM);

    // 0. pre-convert operands to fp16 (hi/lo split for weights)
    cvt_w_kernel<<<448, 256>>>(w_qkv, w_proj);
    cvt_x_kernel<<<65536, 256>>>(x);
    // 1. patchify conv + BN1 (fp16 mma.sync) -> g_qkv
    conv_mma_kernel<<<dim3(6, 512), 256, GEMM_SMEM>>>(gamma1, beta1);
    // 2. transpose q|k|v planes -> g_qkvT
    transpose_kernel<<<dim3(2, 2, 16 * 768), 256>>>();
    // 3. height-axis attention -> g_vP[:, :, 0:256]
    attn_kernel<<<dim3(64, 16), 256, attn_smem>>>(0);
    // 4. width-axis attention  -> g_vP[:, :, 256:512]
    attn_kernel<<<dim3(64, 16), 256, attn_smem>>>(1);
    // 5. 1x1 proj + BN2 + ReLU (fp16 mma.sync) -> out
    proj_mma_kernel<<<dim3(2, 512), 256, GEMM_SMEM>>>(gamma2, beta2, out);
}